// round 10
// baseline (speedup 1.0000x reference)
#include <cuda_runtime.h>
#include <cuda_bf16.h>
#include <math.h>
#include <stdint.h>

#define DIM    1024
#define HD     128
#define FF     4096
#define VOC    2048
#define NLM    15
#define NLAYER 5
#define EPSF   1e-6f
#define NBLK   148
#define CTHR   512          // compute threads
#define NTHR   544          // + producer warp
#define NWARP  16

#define NBUF         13
#define STAGE_BYTES  16384
#define STAGE_FLOATS 4096
#define MBF_OFF  0
#define MBE_OFF  112
#define SC_OFF   224
#define XS_OFF   256
#define SBUF_OFF 4352
#define TAB_OFF  4480        // 240 entries max (~212 used worst case)
#define ST_OFF   8192
#define SM_TOTAL (ST_OFF + NBUF * STAGE_BYTES)   // 221184

#define N_STICKY_MATS 12

// ---------------- device scratch ----------------
__device__ float g_h[2 * DIM];
__device__ float g_qkv[6 * DIM];
__device__ float g_gu[4 * FF];
__device__ unsigned g_bar[32];
__device__ unsigned g_fin;

// ---------------- PTX helpers ----------------
__device__ __forceinline__ uint32_t s2u(const void* p) {
    uint32_t a;
    asm("{ .reg .u64 t; cvta.to.shared.u64 t, %1; cvt.u32.u64 %0, t; }"
        : "=r"(a) : "l"(p));
    return a;
}
#define MB_INIT(mbar, cnt) \
    asm volatile("mbarrier.init.shared.b64 [%0], %1;" :: "r"(mbar), "r"(cnt) : "memory")
#define MB_EXPECT(mbar, bytes) \
    asm volatile("mbarrier.arrive.expect_tx.shared.b64 _, [%0], %1;" :: "r"(mbar), "r"(bytes) : "memory")
#define MB_ARRIVE(mbar) \
    asm volatile("mbarrier.arrive.shared.b64 _, [%0];" :: "r"(mbar) : "memory")
#define MB_WAIT(mbar, ph) do {                                                   \
    asm volatile("{\n\t.reg .pred P1;\n\t"                                       \
        "W_%=:\n\t"                                                              \
        "mbarrier.try_wait.parity.acquire.cta.shared::cta.b64 P1, [%0], %1, 0x989680;\n\t" \
        "@P1 bra.uni D_%=;\n\t"                                                  \
        "bra.uni W_%=;\n\t"                                                      \
        "D_%=:\n\t}"                                                             \
        :: "r"(mbar), "r"(ph) : "memory");                                       \
} while (0)
#define CBAR() asm volatile("bar.sync 1, %0;" :: "n"(CTHR) : "memory")
__device__ __forceinline__ void bulk_g2s_h(uint32_t dst, const void* src,
                                           uint32_t bytes, uint32_t mbar,
                                           uint64_t pol) {
    asm volatile(
        "cp.async.bulk.shared::cluster.global.mbarrier::complete_tx::bytes"
        ".L2::cache_hint [%0], [%1], %2, [%3], %4;"
        :: "r"(dst), "l"(src), "r"(bytes), "r"(mbar), "l"(pol) : "memory");
}
__device__ __forceinline__ void red2(float* p, float a, float b) {
    asm volatile("red.global.add.v2.f32 [%0], {%1, %2};"
                 :: "l"(p), "f"(a), "f"(b) : "memory");
}
__device__ __forceinline__ void red4(float* p, float4 v) {
    asm volatile("red.global.add.v4.f32 [%0], {%1, %2, %3, %4};"
                 :: "l"(p), "f"(v.x), "f"(v.y), "f"(v.z), "f"(v.w) : "memory");
}
__device__ __forceinline__ float ldcg(const float* p) {
    float v;
    asm volatile("ld.global.cg.f32 %0, [%1];" : "=f"(v) : "l"(p));
    return v;
}
__device__ __forceinline__ float4 ldcg4(const float* p) {
    float4 v;
    asm volatile("ld.global.cg.v4.f32 {%0,%1,%2,%3}, [%4];"
                 : "=f"(v.x), "=f"(v.y), "=f"(v.z), "=f"(v.w) : "l"(p));
    return v;
}

// ---------------- reductions ----------------
__device__ __forceinline__ float wred(float v) {
#pragma unroll
    for (int o = 16; o > 0; o >>= 1) v += __shfl_xor_sync(0xffffffffu, v, o);
    return v;
}
__device__ __forceinline__ float bred512(float v, float* sbuf) {
    int tid = threadIdx.x;
#pragma unroll
    for (int o = 16; o > 0; o >>= 1) v += __shfl_down_sync(0xffffffffu, v, o);
    if ((tid & 31) == 0) sbuf[tid >> 5] = v;
    CBAR();
    if (tid < 32) {
        float r = (tid < 16) ? sbuf[tid] : 0.f;
#pragma unroll
        for (int o = 8; o > 0; o >>= 1) r += __shfl_down_sync(0xffffffffu, r, o);
        if (tid == 0) sbuf[0] = r;
    }
    CBAR();
    float r = sbuf[0];
    CBAR();
    return r;
}

__device__ __forceinline__ void gbar(int idx) {
    __threadfence();
    CBAR();
    if (threadIdx.x == 0) {
        atomicAdd(&g_bar[idx], 1u);
        unsigned v;
        while (true) {
            asm volatile("ld.acquire.gpu.global.u32 %0, [%1];"
                         : "=r"(v) : "l"(&g_bar[idx]) : "memory");
            if (v >= (unsigned)NBLK) break;
            __nanosleep(64);
        }
    }
    CBAR();
}

// consume one 16KB stage
#define STAGE_WAIT()                                                           \
    int _slot = consumed % NBUF, _par = (consumed / NBUF) & 1;                 \
    MB_WAIT(mbf + 8u * _slot, _par);                                           \
    const float* buf = (const float*)(sm + ST_OFF + _slot * STAGE_BYTES);
#define STAGE_DONE()                                                           \
    __syncwarp();                                                              \
    if ((tid & 31) == 0) MB_ARRIVE(mbe + 8u * _slot);                          \
    consumed++;

// unit ranges (identical in producer + consumer)
__device__ __forceinline__ void urange(int b, int U, int& u0, int& u1) {
    u0 = (b * U) / NBLK;
    u1 = ((b + 1) * U) / NBLK;
}

// ---------------- mega kernel ----------------
__global__ void __launch_bounds__(NTHR) k_mega(
    const float* __restrict__ past, const float* __restrict__ emb,
    const int* __restrict__ tok,
    const float* __restrict__ Wq, const float* __restrict__ Wk,
    const float* __restrict__ Wv, const float* __restrict__ Wo,
    const float* __restrict__ qn, const float* __restrict__ kn,
    const float* __restrict__ ln1, const float* __restrict__ ln2,
    const float* __restrict__ Wg, const float* __restrict__ Wu,
    const float* __restrict__ Wd, const float* __restrict__ fn,
    const float* __restrict__ lm,
    float* __restrict__ logits, float* __restrict__ kvc) {
    extern __shared__ char sm[];
    const int b = blockIdx.x;
    const int tid = threadIdx.x;
    const uint32_t mbf = s2u(sm) + MBF_OFF;
    const uint32_t mbe = s2u(sm) + MBE_OFF;
    float* sbuf = (float*)(sm + SBUF_OFF);
    float2* xs2 = (float2*)(sm + XS_OFF);
    float* xsf = (float*)(sm + XS_OFF);
    float* sc = (float*)(sm + SC_OFF);

    if (tid == CTHR) {
#pragma unroll
        for (int s = 0; s < NBUF; s++) {
            MB_INIT(mbf + 8u * s, 1);
            MB_INIT(mbe + 8u * s, NWARP);
        }
    }
    __syncthreads();

    // ================= producer warp =================
    if (tid >= CTHR) {
        if (tid == CTHR) {
            uint64_t pol_keep, pol_stream;
            asm volatile("createpolicy.fractional.L2::evict_last.b64 %0, 1.0;"
                         : "=l"(pol_keep));
            asm volatile("createpolicy.fractional.L2::evict_first.b64 %0, 1.0;"
                         : "=l"(pol_stream));
            uintptr_t* tab = (uintptr_t*)(sm + TAB_OFF);
            int n = 0;
            int u0, u1;
            for (int l = 0; l < NLAYER; l++) {
                // QKV: 384 units, 8 rows x 1024, 2 stages
                urange(b, 384, u0, u1);
                for (int u = u0; u < u1; u++) {
                    int mat = u >> 7;
                    const float* W = mat == 0 ? Wq : (mat == 1 ? Wk : Wv);
                    const float* base = W + (size_t)l * DIM * DIM +
                                        (size_t)(u & 127) * 8 * DIM;
                    tab[n++] = (uintptr_t)base;
                    tab[n++] = (uintptr_t)(base + STAGE_FLOATS);
                }
                // WO: 128 units, 8 rows x 1024, 2 stages
                urange(b, 128, u0, u1);
                for (int u = u0; u < u1; u++) {
                    const float* base = Wo + (size_t)l * DIM * DIM +
                                        (size_t)u * 8 * DIM;
                    tab[n++] = (uintptr_t)base;
                    tab[n++] = (uintptr_t)(base + STAGE_FLOATS);
                }
                // GATEUP: 512 units, 4 rows x 4096, 4 stages
                urange(b, 512, u0, u1);
                for (int u = u0; u < u1; u++) {
                    const float* W = (u >> 8) ? Wu : Wg;
                    const float* base = W + (size_t)l * DIM * FF +
                                        (size_t)(u & 255) * 4 * FF;
                    for (int s = 0; s < 4; s++)
                        tab[n++] = (uintptr_t)(base + (size_t)s * STAGE_FLOATS);
                }
                // DOWN: 512 units, 8 rows x 1024, 2 stages
                urange(b, 512, u0, u1);
                for (int u = u0; u < u1; u++) {
                    const float* base = Wd + (size_t)l * FF * DIM +
                                        (size_t)u * 8 * DIM;
                    tab[n++] = (uintptr_t)base;
                    tab[n++] = (uintptr_t)(base + STAGE_FLOATS);
                }
            }
            // LM: 1920 units, 8 rows x 2048, 4 stages
            urange(b, 1920, u0, u1);
            for (int u = u0; u < u1; u++) {
                int mat = u >> 7;
                uintptr_t flag = (mat < N_STICKY_MATS) ? 1u : 0u;
                const float* base = lm + (size_t)mat * DIM * VOC +
                                    (size_t)(u & 127) * 8 * VOC;
                for (int s = 0; s < 4; s++)
                    tab[n++] = ((uintptr_t)(base + (size_t)s * STAGE_FLOATS)) | flag;
            }
            for (int i = 0; i < n; i++) {
                int slot = i % NBUF;
                if (i >= NBUF) {
                    int par = ((i / NBUF) - 1) & 1;
                    MB_WAIT(mbe + 8u * slot, par);
                }
                uintptr_t e = tab[i];
                uint64_t pol = (e & 1u) ? pol_keep : pol_stream;
                const void* src = (const void*)(e & ~(uintptr_t)1u);
                MB_EXPECT(mbf + 8u * slot, STAGE_BYTES);
                bulk_g2s_h(s2u(sm) + ST_OFF + slot * STAGE_BYTES, src,
                           STAGE_BYTES, mbf + 8u * slot, pol);
            }
        }
        return;
    }

    // ================= compute threads (512) =================
    int consumed = 0;
    int u0, u1;

    {   // init: zero logits/qkv, embed
        int gi = b * CTHR + tid;
        if (gi < NLM * VOC) logits[gi] = 0.f;
        else if (gi < NLM * VOC + 6 * DIM) g_qkv[gi - NLM * VOC] = 0.f;
        else if (gi < NLM * VOC + 6 * DIM + DIM) {
            int i = gi - (NLM * VOC + 6 * DIM);
            g_h[i] = past[i];
        } else if (gi < NLM * VOC + 6 * DIM + 2 * DIM) {
            int i = gi - (NLM * VOC + 7 * DIM);
            g_h[DIM + i] = emb[(size_t)tok[0] * DIM + i];
        }
    }
    gbar(0);

    for (int l = 0; l < NLAYER; l++) {
        // ===== QKV (all blocks) =====
        {
            float s0 = 0.f, s1 = 0.f;
#pragma unroll
            for (int i = 0; i < 2; i++) {
                int idx = tid + i * CTHR;
                float a = ldcg(&g_h[idx]), c = ldcg(&g_h[DIM + idx]);
                s0 += a * a; s1 += c * c;
            }
            s0 = bred512(s0, sbuf);
            s1 = bred512(s1, sbuf);
            float r0 = rsqrtf(s0 * (1.f / DIM) + EPSF);
            float r1 = rsqrtf(s1 * (1.f / DIM) + EPSF);
            // zero g_gu for this layer's gateup (blocks 0..31 cover it)
            if (b * CTHR + tid < 4 * FF) g_gu[b * CTHR + tid] = 0.f;

            urange(b, 384, u0, u1);
            for (int u = u0; u < u1; u++) {
                int mat = u >> 7, rowbase = (u & 127) * 8;
                CBAR();
                if (tid < 8) {
                    int idx = rowbase + tid;
                    float wl = ln1[l * DIM + idx];
                    xs2[tid] = make_float2(ldcg(&g_h[idx]) * r0 * wl,
                                           ldcg(&g_h[DIM + idx]) * r1 * wl);
                }
                CBAR();
                float a00 = 0.f, a01 = 0.f, a10 = 0.f, a11 = 0.f;
                for (int st = 0; st < 2; st++) {
                    STAGE_WAIT()
                    const float2* bw = (const float2*)buf;
#pragma unroll
                    for (int r = 0; r < 4; r++) {
                        float2 w = bw[r * CTHR + tid];
                        float2 x = xs2[st * 4 + r];
                        a00 = fmaf(w.x, x.x, a00); a01 = fmaf(w.y, x.x, a01);
                        a10 = fmaf(w.x, x.y, a10); a11 = fmaf(w.y, x.y, a11);
                    }
                    STAGE_DONE()
                }
                float* o = g_qkv + mat * 2048;
                red2(o + 2 * tid, a00, a01);
                red2(o + DIM + 2 * tid, a10, a11);
            }
        }
        gbar(1 + 4 * l);

        // ===== WO + attention (all blocks) =====
        {
            urange(b, 128, u0, u1);
            for (int u = u0; u < u1; u++) {
                int hh = u >> 4, rowbase = u * 8;
                CBAR();
                if (tid < 32) {
                    int lane = tid;
                    float4 q1 = ldcg4(g_qkv + DIM + hh * HD + 4 * lane);
                    float4 k0 = ldcg4(g_qkv + 2048 + hh * HD + 4 * lane);
                    float4 k1 = ldcg4(g_qkv + 2048 + DIM + hh * HD + 4 * lane);
                    float nq1 = wred(q1.x * q1.x + q1.y * q1.y + q1.z * q1.z + q1.w * q1.w);
                    float nk0 = wred(k0.x * k0.x + k0.y * k0.y + k0.z * k0.z + k0.w * k0.w);
                    float nk1 = wred(k1.x * k1.x + k1.y * k1.y + k1.z * k1.z + k1.w * k1.w);
                    float rq1 = rsqrtf(nq1 * (1.f / HD) + EPSF);
                    float rk0 = rsqrtf(nk0 * (1.f / HD) + EPSF);
                    float rk1 = rsqrtf(nk1 * (1.f / HD) + EPSF);
                    float4 qn4 = ((const float4*)(qn + l * HD))[lane];
                    float4 kn4 = ((const float4*)(kn + l * HD))[lane];
                    q1.x *= rq1 * qn4.x; q1.y *= rq1 * qn4.y;
                    q1.z *= rq1 * qn4.z; q1.w *= rq1 * qn4.w;
                    k0.x *= rk0 * kn4.x; k0.y *= rk0 * kn4.y;
                    k0.z *= rk0 * kn4.z; k0.w *= rk0 * kn4.w;
                    k1.x *= rk1 * kn4.x; k1.y *= rk1 * kn4.y;
                    k1.z *= rk1 * kn4.z; k1.w *= rk1 * kn4.w;
                    int jb = 4 * (lane & 15);
                    const float C = 9.210340371976184f / 64.f;
                    float an0 = expf(-(float)(jb + 0) * C);
                    float an1 = expf(-(float)(jb + 1) * C);
                    float an2 = expf(-(float)(jb + 2) * C);
                    float an3 = expf(-(float)(jb + 3) * C);
                    float csx = cosf(an0), snx = sinf(an0);
                    float csy = cosf(an1), sny = sinf(an1);
                    float csz = cosf(an2), snz = sinf(an2);
                    float csw = cosf(an3), snw = sinf(an3);
                    float sgn = (lane < 16) ? -1.f : 1.f;
                    float4 pq, pk;
                    pq.x = __shfl_xor_sync(0xffffffffu, q1.x, 16);
                    pq.y = __shfl_xor_sync(0xffffffffu, q1.y, 16);
                    pq.z = __shfl_xor_sync(0xffffffffu, q1.z, 16);
                    pq.w = __shfl_xor_sync(0xffffffffu, q1.w, 16);
                    pk.x = __shfl_xor_sync(0xffffffffu, k1.x, 16);
                    pk.y = __shfl_xor_sync(0xffffffffu, k1.y, 16);
                    pk.z = __shfl_xor_sync(0xffffffffu, k1.z, 16);
                    pk.w = __shfl_xor_sync(0xffffffffu, k1.w, 16);
                    q1.x = q1.x * csx + sgn * pq.x * snx;
                    q1.y = q1.y * csy + sgn * pq.y * sny;
                    q1.z = q1.z * csz + sgn * pq.z * snz;
                    q1.w = q1.w * csw + sgn * pq.w * snw;
                    k1.x = k1.x * csx + sgn * pk.x * snx;
                    k1.y = k1.y * csy + sgn * pk.y * sny;
                    k1.z = k1.z * csz + sgn * pk.z * snz;
                    k1.w = k1.w * csw + sgn * pk.w * snw;
                    float d10 = wred(q1.x * k0.x + q1.y * k0.y + q1.z * k0.z + q1.w * k0.w);
                    float d11 = wred(q1.x * k1.x + q1.y * k1.y + q1.z * k1.z + q1.w * k1.w);
                    const float scale = 0.08838834764831845f;
                    float s10 = d10 * scale, s11 = d11 * scale;
                    float m = fmaxf(s10, s11);
                    float e0 = expf(s10 - m), e1 = expf(s11 - m);
                    float inv = 1.f / (e0 + e1);
                    if (lane == 0) { sc[0] = e0; sc[1] = e1; sc[2] = inv; }
                    if ((u & 15) == 0) {
                        float4 v0 = ldcg4(g_qkv + 4096 + hh * HD + 4 * lane);
                        float4 v1 = ldcg4(g_qkv + 4096 + DIM + hh * HD + 4 * lane);
                        float* kv = kvc + (size_t)l * 4096;
                        ((float4*)(kv + hh * 256))[lane] = k0;
                        ((float4*)(kv + hh * 256 + HD))[lane] = k1;
                        ((float4*)(kv + 2048 + hh * 256))[lane] = v0;
                        ((float4*)(kv + 2048 + hh * 256 + HD))[lane] = v1;
                    }
                    __syncwarp();
                    if (lane < 8) {
                        int dim = rowbase + lane;
                        float v0 = ldcg(&g_qkv[4096 + dim]);
                        float v1 = ldcg(&g_qkv[4096 + DIM + dim]);
                        xs2[lane] = make_float2(v0, (sc[0] * v0 + sc[1] * v1) * sc[2]);
                    }
                }
                CBAR();
                float a00 = 0.f, a01 = 0.f, a10 = 0.f, a11 = 0.f;
                for (int st = 0; st < 2; st++) {
                    STAGE_WAIT()
                    const float2* bw = (const float2*)buf;
#pragma unroll
                    for (int r = 0; r < 4; r++) {
                        float2 w = bw[r * CTHR + tid];
                        float2 x = xs2[st * 4 + r];
                        a00 = fmaf(w.x, x.x, a00); a01 = fmaf(w.y, x.x, a01);
                        a10 = fmaf(w.x, x.y, a10); a11 = fmaf(w.y, x.y, a11);
                    }
                    STAGE_DONE()
                }
                red2(g_h + 2 * tid, a00, a01);
                red2(g_h + DIM + 2 * tid, a10, a11);
            }
        }
        gbar(2 + 4 * l);

        // ===== GATEUP (all blocks) =====
        {
            float s0 = 0.f, s1 = 0.f;
#pragma unroll
            for (int i = 0; i < 2; i++) {
                int idx = tid + i * CTHR;
                float a = ldcg(&g_h[idx]), c = ldcg(&g_h[DIM + idx]);
                s0 += a * a; s1 += c * c;
            }
            s0 = bred512(s0, sbuf);
            s1 = bred512(s1, sbuf);
            float r0 = rsqrtf(s0 * (1.f / DIM) + EPSF);
            float r1 = rsqrtf(s1 * (1.f / DIM) + EPSF);
            // zero g_qkv for next layer (blocks 0..11)
            if (b * CTHR + tid < 6 * DIM) g_qkv[b * CTHR + tid] = 0.f;

            urange(b, 512, u0, u1);
            for (int u = u0; u < u1; u++) {
                int mat = u >> 8, rowbase = (u & 255) * 4;
                CBAR();
                if (tid < 4) {
                    int idx = rowbase + tid;
                    float wl = ln2[l * DIM + idx];
                    xs2[tid] = make_float2(ldcg(&g_h[idx]) * r0 * wl,
                                           ldcg(&g_h[DIM + idx]) * r1 * wl);
                }
                CBAR();
                float4 A00 = {0,0,0,0}, A01 = {0,0,0,0},
                       A10 = {0,0,0,0}, A11 = {0,0,0,0};
                for (int st = 0; st < 4; st++) {
                    STAGE_WAIT()
                    const float4* b4 = (const float4*)buf;
                    float2 x = xs2[st];
                    float4 w0 = b4[tid];
                    float4 w1 = b4[CTHR + tid];
                    A00.x = fmaf(w0.x, x.x, A00.x); A00.y = fmaf(w0.y, x.x, A00.y);
                    A00.z = fmaf(w0.z, x.x, A00.z); A00.w = fmaf(w0.w, x.x, A00.w);
                    A10.x = fmaf(w0.x, x.y, A10.x); A10.y = fmaf(w0.y, x.y, A10.y);
                    A10.z = fmaf(w0.z, x.y, A10.z); A10.w = fmaf(w0.w, x.y, A10.w);
                    A01.x = fmaf(w1.x, x.x, A01.x); A01.y = fmaf(w1.y, x.x, A01.y);
                    A01.z = fmaf(w1.z, x.x, A01.z); A01.w = fmaf(w1.w, x.x, A01.w);
                    A11.x = fmaf(w1.x, x.y, A11.x); A11.y = fmaf(w1.y, x.y, A11.y);
                    A11.z = fmaf(w1.z, x.y, A11.z); A11.w = fmaf(w1.w, x.y, A11.w);
                    STAGE_DONE()
                }
                float* o = g_gu + mat * 8192;
                red4(o + 4 * tid, A00);
                red4(o + 2048 + 4 * tid, A01);
                red4(o + FF + 4 * tid, A10);
                red4(o + FF + 2048 + 4 * tid, A11);
            }
        }
        gbar(3 + 4 * l);

        // ===== DOWN (all blocks) =====
        {
            urange(b, 512, u0, u1);
            for (int u = u0; u < u1; u++) {
                int rowbase = u * 8;
                CBAR();
                if (tid < 8) {
                    int idx = rowbase + tid;
                    float g0 = ldcg(&g_gu[idx]);
                    float g1 = ldcg(&g_gu[FF + idx]);
                    float v0 = ldcg(&g_gu[8192 + idx]);
                    float v1 = ldcg(&g_gu[8192 + FF + idx]);
                    xs2[tid] = make_float2(g0 / (1.f + expf(-g0)) * v0,
                                           g1 / (1.f + expf(-g1)) * v1);
                }
                CBAR();
                float a00 = 0.f, a01 = 0.f, a10 = 0.f, a11 = 0.f;
                for (int st = 0; st < 2; st++) {
                    STAGE_WAIT()
                    const float2* bw = (const float2*)buf;
#pragma unroll
                    for (int r = 0; r < 4; r++) {
                        float2 w = bw[r * CTHR + tid];
                        float2 x = xs2[st * 4 + r];
                        a00 = fmaf(w.x, x.x, a00); a01 = fmaf(w.y, x.x, a01);
                        a10 = fmaf(w.x, x.y, a10); a11 = fmaf(w.y, x.y, a11);
                    }
                    STAGE_DONE()
                }
                red2(g_h + 2 * tid, a00, a01);
                red2(g_h + DIM + 2 * tid, a10, a11);
            }
        }
        gbar(4 + 4 * l);
    }

    // ===== LM (all blocks) =====
    {
        float s = 0.f;
#pragma unroll
        for (int i = 0; i < 2; i++) {
            float v = ldcg(&g_h[DIM + tid + i * CTHR]);
            s += v * v;
        }
        s = bred512(s, sbuf);
        float r = rsqrtf(s * (1.f / DIM) + EPSF);
#pragma unroll
        for (int i = 0; i < 2; i++) {
            int idx = tid + i * CTHR;
            xsf[idx] = ldcg(&g_h[DIM + idx]) * r * fn[idx];
        }
        CBAR();

        urange(b, 1920, u0, u1);
        for (int u = u0; u < u1; u++) {
            int mat = u >> 7, rowbase = (u & 127) * 8;
            float4 A = {0, 0, 0, 0};
            for (int st = 0; st < 4; st++) {
                STAGE_WAIT()
                const float4* b4 = (const float4*)buf;
#pragma unroll
                for (int r2 = 0; r2 < 2; r2++) {
                    float x = xsf[rowbase + st * 2 + r2];
                    float4 w = b4[r2 * CTHR + tid];
                    A.x = fmaf(w.x, x, A.x); A.y = fmaf(w.y, x, A.y);
                    A.z = fmaf(w.z, x, A.z); A.w = fmaf(w.w, x, A.w);
                }
                STAGE_DONE()
            }
            red4(logits + (size_t)mat * VOC + 4 * tid, A);
        }
    }

    CBAR();
    if (tid == 0) {
        unsigned old = atomicAdd(&g_fin, 1u);
        if (old == (unsigned)(NBLK - 1)) {
            for (int i = 0; i < 21; i++) g_bar[i] = 0u;
            __threadfence();
            g_fin = 0u;
        }
    }
}

// ---------------- host launcher ----------------
extern "C" void kernel_launch(void* const* d_in, const int* in_sizes, int n_in,
                              void* d_out, int out_size) {
    const float *past, *emb, *Wq, *Wk, *Wv, *Wo, *qn, *kn, *ln1, *ln2, *Wg, *Wu,
        *Wd, *fn, *lm;
    const int* tok;
    if (in_sizes[1] == 1) {
        past = (const float*)d_in[0];
        tok  = (const int*)d_in[1];
        emb  = (const float*)d_in[2];
        Wq = (const float*)d_in[3];  Wk = (const float*)d_in[4];
        Wv = (const float*)d_in[5];  Wo = (const float*)d_in[6];
        qn = (const float*)d_in[7];  kn = (const float*)d_in[8];
        ln1 = (const float*)d_in[9]; ln2 = (const float*)d_in[10];
        Wg = (const float*)d_in[11]; Wu = (const float*)d_in[12];
        Wd = (const float*)d_in[13]; fn = (const float*)d_in[14];
        lm = (const float*)d_in[15];
    } else {
        past = (const float*)d_in[0];
        emb  = (const float*)d_in[1];
        Wq = (const float*)d_in[2];  Wk = (const float*)d_in[3];
        Wv = (const float*)d_in[4];  Wo = (const float*)d_in[5];
        qn = (const float*)d_in[6];  kn = (const float*)d_in[7];
        ln1 = (const float*)d_in[8]; ln2 = (const float*)d_in[9];
        Wg = (const float*)d_in[10]; Wu = (const float*)d_in[11];
        Wd = (const float*)d_in[12]; fn = (const float*)d_in[13];
        lm = (const float*)d_in[14];
        tok = (const int*)d_in[15];
    }

    static bool attr_done = false;
    if (!attr_done) {
        cudaFuncSetAttribute(k_mega, cudaFuncAttributeMaxDynamicSharedMemorySize,
                             SM_TOTAL);
        attr_done = true;
    }

    float* out = (float*)d_out;
    float* logits = out;
    float* kvc = out + NLM * VOC;

    k_mega<<<NBLK, NTHR, SM_TOTAL>>>(past, emb, tok, Wq, Wk, Wv, Wo, qn, kn,
                                     ln1, ln2, Wg, Wu, Wd, fn, lm, logits, kvc);
    (void)n_in; (void)out_size;
}

// round 11
// speedup vs baseline: 1.2462x; 1.2462x over previous
#include <cuda_runtime.h>
#include <cuda_bf16.h>
#include <math.h>
#include <stdint.h>

#define DIM    1024
#define HD     128
#define FF     4096
#define VOC    2048
#define NLM    15
#define NLAYER 5
#define EPSF   1e-6f
#define NBLK   296           // 2 CTAs per SM
#define CTHR   256           // compute threads
#define NTHR   288           // + producer warp
#define NWARP  8

#define NBUF         6
#define STAGE_BYTES  16384
#define STAGE_FLOATS 4096
#define MBF_OFF  0
#define MBE_OFF  64
#define SC_OFF   128
#define XS_OFF   256         // xs/xsf up to 4KB
#define SBUF_OFF 4352
#define TAB_OFF  4480        // 240 ptrs
#define ST_OFF   8192
#define SM_TOTAL (ST_OFF + NBUF * STAGE_BYTES)   // 106496

#define N_STICKY_MATS 12

// ---------------- device scratch ----------------
__device__ float g_h[2 * DIM];
__device__ float g_qkv[6 * DIM];
__device__ float g_gu[4 * FF];
__device__ unsigned g_bar[32];
__device__ unsigned g_fin;

// ---------------- PTX helpers ----------------
__device__ __forceinline__ uint32_t s2u(const void* p) {
    uint32_t a;
    asm("{ .reg .u64 t; cvta.to.shared.u64 t, %1; cvt.u32.u64 %0, t; }"
        : "=r"(a) : "l"(p));
    return a;
}
#define MB_INIT(mbar, cnt) \
    asm volatile("mbarrier.init.shared.b64 [%0], %1;" :: "r"(mbar), "r"(cnt) : "memory")
#define MB_EXPECT(mbar, bytes) \
    asm volatile("mbarrier.arrive.expect_tx.shared.b64 _, [%0], %1;" :: "r"(mbar), "r"(bytes) : "memory")
#define MB_ARRIVE(mbar) \
    asm volatile("mbarrier.arrive.shared.b64 _, [%0];" :: "r"(mbar) : "memory")
#define MB_WAIT(mbar, ph) do {                                                   \
    asm volatile("{\n\t.reg .pred P1;\n\t"                                       \
        "W_%=:\n\t"                                                              \
        "mbarrier.try_wait.parity.acquire.cta.shared::cta.b64 P1, [%0], %1, 0x989680;\n\t" \
        "@P1 bra.uni D_%=;\n\t"                                                  \
        "bra.uni W_%=;\n\t"                                                      \
        "D_%=:\n\t}"                                                             \
        :: "r"(mbar), "r"(ph) : "memory");                                       \
} while (0)
#define CBAR() asm volatile("bar.sync 1, %0;" :: "n"(CTHR) : "memory")
__device__ __forceinline__ void bulk_g2s_h(uint32_t dst, const void* src,
                                           uint32_t bytes, uint32_t mbar,
                                           uint64_t pol) {
    asm volatile(
        "cp.async.bulk.shared::cluster.global.mbarrier::complete_tx::bytes"
        ".L2::cache_hint [%0], [%1], %2, [%3], %4;"
        :: "r"(dst), "l"(src), "r"(bytes), "r"(mbar), "l"(pol) : "memory");
}
__device__ __forceinline__ void red4(float* p, float4 v) {
    asm volatile("red.global.add.v4.f32 [%0], {%1, %2, %3, %4};"
                 :: "l"(p), "f"(v.x), "f"(v.y), "f"(v.z), "f"(v.w) : "memory");
}
__device__ __forceinline__ float ldcg(const float* p) {
    float v;
    asm volatile("ld.global.cg.f32 %0, [%1];" : "=f"(v) : "l"(p));
    return v;
}
__device__ __forceinline__ float4 ldcg4(const float* p) {
    float4 v;
    asm volatile("ld.global.cg.v4.f32 {%0,%1,%2,%3}, [%4];"
                 : "=f"(v.x), "=f"(v.y), "=f"(v.z), "=f"(v.w) : "l"(p));
    return v;
}

// ---------------- reductions ----------------
__device__ __forceinline__ float wred(float v) {
#pragma unroll
    for (int o = 16; o > 0; o >>= 1) v += __shfl_xor_sync(0xffffffffu, v, o);
    return v;
}
__device__ __forceinline__ float bred256(float v, float* sbuf) {
    int tid = threadIdx.x;
#pragma unroll
    for (int o = 16; o > 0; o >>= 1) v += __shfl_down_sync(0xffffffffu, v, o);
    if ((tid & 31) == 0) sbuf[tid >> 5] = v;
    CBAR();
    if (tid < 32) {
        float r = (tid < 8) ? sbuf[tid] : 0.f;
#pragma unroll
        for (int o = 4; o > 0; o >>= 1) r += __shfl_down_sync(0xffffffffu, r, o);
        if (tid == 0) sbuf[0] = r;
    }
    CBAR();
    float r = sbuf[0];
    CBAR();
    return r;
}

__device__ __forceinline__ void gbar(int idx) {
    __threadfence();
    CBAR();
    if (threadIdx.x == 0) {
        atomicAdd(&g_bar[idx], 1u);
        unsigned v;
        while (true) {
            asm volatile("ld.acquire.gpu.global.u32 %0, [%1];"
                         : "=r"(v) : "l"(&g_bar[idx]) : "memory");
            if (v >= (unsigned)NBLK) break;
            __nanosleep(64);
        }
    }
    CBAR();
}

// consume one 16KB stage (per-warp arrivals)
#define STAGE_WAIT()                                                           \
    int _slot = consumed % NBUF, _par = (consumed / NBUF) & 1;                 \
    MB_WAIT(mbf + 8u * _slot, _par);                                           \
    const float* buf = (const float*)(sm + ST_OFF + _slot * STAGE_BYTES);
#define STAGE_DONE()                                                           \
    __syncwarp();                                                              \
    if ((tid & 31) == 0) MB_ARRIVE(mbe + 8u * _slot);                          \
    consumed++;

// ---------------- mega kernel ----------------
__global__ void __launch_bounds__(NTHR) k_mega(
    const float* __restrict__ past, const float* __restrict__ emb,
    const int* __restrict__ tok,
    const float* __restrict__ Wq, const float* __restrict__ Wk,
    const float* __restrict__ Wv, const float* __restrict__ Wo,
    const float* __restrict__ qn, const float* __restrict__ kn,
    const float* __restrict__ ln1, const float* __restrict__ ln2,
    const float* __restrict__ Wg, const float* __restrict__ Wu,
    const float* __restrict__ Wd, const float* __restrict__ fn,
    const float* __restrict__ lm,
    float* __restrict__ logits, float* __restrict__ kvc) {
    extern __shared__ char sm[];
    const int b = blockIdx.x;
    const int tid = threadIdx.x;
    const uint32_t mbf = s2u(sm) + MBF_OFF;
    const uint32_t mbe = s2u(sm) + MBE_OFF;
    float* sbuf = (float*)(sm + SBUF_OFF);
    float2* xs2 = (float2*)(sm + XS_OFF);
    float* xsf = (float*)(sm + XS_OFF);
    float* sc = (float*)(sm + SC_OFF);
    int c0 = (b * 960) / NBLK, c1 = ((b + 1) * 960) / NBLK;   // lm chunks

    if (tid == CTHR) {
#pragma unroll
        for (int s = 0; s < NBUF; s++) {
            MB_INIT(mbf + 8u * s, 1);
            MB_INIT(mbe + 8u * s, NWARP);
        }
    }
    __syncthreads();

    // ================= producer warp =================
    if (tid >= CTHR) {
        if (tid == CTHR) {
            uint64_t pol_keep, pol_stream;
            asm volatile("createpolicy.fractional.L2::evict_last.b64 %0, 1.0;"
                         : "=l"(pol_keep));
            asm volatile("createpolicy.fractional.L2::evict_first.b64 %0, 1.0;"
                         : "=l"(pol_stream));
            uintptr_t* tab = (uintptr_t*)(sm + TAB_OFF);
            int n = 0;
            for (int l = 0; l < NLAYER; l++) {
                if (b < 192) {   // QKV: 16 rows, 4 stages
                    int mat = b / 64;
                    const float* W = mat == 0 ? Wq : (mat == 1 ? Wk : Wv);
                    const float* base = W + (size_t)l * DIM * DIM +
                                        (size_t)(b % 64) * 16 * DIM;
                    for (int s = 0; s < 4; s++)
                        tab[n++] = (uintptr_t)(base + (size_t)s * STAGE_FLOATS);
                }
                if (b < 128) {   // WO: 8 rows, 2 stages
                    const float* base = Wo + (size_t)l * DIM * DIM +
                                        (size_t)b * 8 * DIM;
                    tab[n++] = (uintptr_t)base;
                    tab[n++] = (uintptr_t)(base + STAGE_FLOATS);
                }
                if (b < 256) {   // GATEUP: 8 rows x 4096, 8 stages (1 row each)
                    const float* W = (b >> 7) ? Wu : Wg;
                    const float* base = W + (size_t)l * DIM * FF +
                                        (size_t)(b & 127) * 8 * FF;
                    for (int s = 0; s < 8; s++)
                        tab[n++] = (uintptr_t)(base + (size_t)s * STAGE_FLOATS);
                }
                if (b < 256) {   // DOWN: 16 rows, 4 stages
                    const float* base = Wd + (size_t)l * FF * DIM +
                                        (size_t)b * 16 * DIM;
                    for (int s = 0; s < 4; s++)
                        tab[n++] = (uintptr_t)(base + (size_t)s * STAGE_FLOATS);
                }
            }
            for (int c = c0; c < c1; c++) {   // LM: 16 rows x 2048, 8 stages
                int mat = c >> 6;
                uintptr_t flag = (mat < N_STICKY_MATS) ? 1u : 0u;
                const float* base = lm + (size_t)mat * DIM * VOC +
                                    (size_t)(c & 63) * 16 * VOC;
                for (int s = 0; s < 8; s++)
                    tab[n++] = ((uintptr_t)(base + (size_t)s * STAGE_FLOATS)) | flag;
            }
            for (int i = 0; i < n; i++) {
                int slot = i % NBUF;
                if (i >= NBUF) {
                    int par = ((i / NBUF) - 1) & 1;
                    MB_WAIT(mbe + 8u * slot, par);
                }
                uintptr_t e = tab[i];
                uint64_t pol = (e & 1u) ? pol_keep : pol_stream;
                const void* src = (const void*)(e & ~(uintptr_t)1u);
                MB_EXPECT(mbf + 8u * slot, STAGE_BYTES);
                bulk_g2s_h(s2u(sm) + ST_OFF + slot * STAGE_BYTES, src,
                           STAGE_BYTES, mbf + 8u * slot, pol);
            }
        }
        return;
    }

    // ================= compute threads (256) =================
    int consumed = 0;

    {   // init
        int gi = b * CTHR + tid;
        if (gi < NLM * VOC) logits[gi] = 0.f;
        else if (gi < NLM * VOC + 6 * DIM) g_qkv[gi - NLM * VOC] = 0.f;
        else if (gi < NLM * VOC + 6 * DIM + DIM) {
            int i = gi - (NLM * VOC + 6 * DIM);
            g_h[i] = past[i];
        } else if (gi < NLM * VOC + 6 * DIM + 2 * DIM) {
            int i = gi - (NLM * VOC + 7 * DIM);
            g_h[DIM + i] = emb[(size_t)tok[0] * DIM + i];
        }
    }
    gbar(0);

    for (int l = 0; l < NLAYER; l++) {
        // ===== QKV (b<192); b in [192,256) zeroes g_gu =====
        if (b < 192) {
            int mat = b / 64, rch = b % 64;
            float s0 = 0.f, s1 = 0.f;
#pragma unroll
            for (int i = 0; i < 4; i++) {
                int idx = tid + i * CTHR;
                float a = ldcg(&g_h[idx]), c = ldcg(&g_h[DIM + idx]);
                s0 += a * a; s1 += c * c;
            }
            s0 = bred256(s0, sbuf);
            s1 = bred256(s1, sbuf);
            float r0 = rsqrtf(s0 * (1.f / DIM) + EPSF);
            float r1 = rsqrtf(s1 * (1.f / DIM) + EPSF);
            if (tid < 16) {
                int idx = rch * 16 + tid;
                float wl = ln1[l * DIM + idx];
                xs2[tid] = make_float2(ldcg(&g_h[idx]) * r0 * wl,
                                       ldcg(&g_h[DIM + idx]) * r1 * wl);
            }
            CBAR();
            float4 A0 = {0,0,0,0}, A1 = {0,0,0,0};
            for (int st = 0; st < 4; st++) {
                STAGE_WAIT()
                const float4* b4 = (const float4*)buf;
#pragma unroll
                for (int r = 0; r < 4; r++) {
                    float4 w = b4[r * CTHR + tid];
                    float2 x = xs2[st * 4 + r];
                    A0.x = fmaf(w.x, x.x, A0.x); A0.y = fmaf(w.y, x.x, A0.y);
                    A0.z = fmaf(w.z, x.x, A0.z); A0.w = fmaf(w.w, x.x, A0.w);
                    A1.x = fmaf(w.x, x.y, A1.x); A1.y = fmaf(w.y, x.y, A1.y);
                    A1.z = fmaf(w.z, x.y, A1.z); A1.w = fmaf(w.w, x.y, A1.w);
                }
                STAGE_DONE()
            }
            float* o = g_qkv + mat * 2048;
            red4(o + 4 * tid, A0);
            red4(o + DIM + 4 * tid, A1);
        } else if (b < 256) {
            g_gu[(b - 192) * CTHR + tid] = 0.f;   // 64 x 256 = 16384 ✓
        }
        gbar(1 + 4 * l);

        // ===== WO + attention (b<128) =====
        if (b < 128) {
            int hh = b >> 4;
            if (tid < 32) {
                int lane = tid;
                float4 q1 = ldcg4(g_qkv + DIM + hh * HD + 4 * lane);
                float4 k0 = ldcg4(g_qkv + 2048 + hh * HD + 4 * lane);
                float4 k1 = ldcg4(g_qkv + 2048 + DIM + hh * HD + 4 * lane);
                float nq1 = wred(q1.x * q1.x + q1.y * q1.y + q1.z * q1.z + q1.w * q1.w);
                float nk0 = wred(k0.x * k0.x + k0.y * k0.y + k0.z * k0.z + k0.w * k0.w);
                float nk1 = wred(k1.x * k1.x + k1.y * k1.y + k1.z * k1.z + k1.w * k1.w);
                float rq1 = rsqrtf(nq1 * (1.f / HD) + EPSF);
                float rk0 = rsqrtf(nk0 * (1.f / HD) + EPSF);
                float rk1 = rsqrtf(nk1 * (1.f / HD) + EPSF);
                float4 qn4 = ((const float4*)(qn + l * HD))[lane];
                float4 kn4 = ((const float4*)(kn + l * HD))[lane];
                q1.x *= rq1 * qn4.x; q1.y *= rq1 * qn4.y;
                q1.z *= rq1 * qn4.z; q1.w *= rq1 * qn4.w;
                k0.x *= rk0 * kn4.x; k0.y *= rk0 * kn4.y;
                k0.z *= rk0 * kn4.z; k0.w *= rk0 * kn4.w;
                k1.x *= rk1 * kn4.x; k1.y *= rk1 * kn4.y;
                k1.z *= rk1 * kn4.z; k1.w *= rk1 * kn4.w;
                int jb = 4 * (lane & 15);
                const float C = 9.210340371976184f / 64.f;
                float an0 = expf(-(float)(jb + 0) * C);
                float an1 = expf(-(float)(jb + 1) * C);
                float an2 = expf(-(float)(jb + 2) * C);
                float an3 = expf(-(float)(jb + 3) * C);
                float csx = cosf(an0), snx = sinf(an0);
                float csy = cosf(an1), sny = sinf(an1);
                float csz = cosf(an2), snz = sinf(an2);
                float csw = cosf(an3), snw = sinf(an3);
                float sgn = (lane < 16) ? -1.f : 1.f;
                float4 pq, pk;
                pq.x = __shfl_xor_sync(0xffffffffu, q1.x, 16);
                pq.y = __shfl_xor_sync(0xffffffffu, q1.y, 16);
                pq.z = __shfl_xor_sync(0xffffffffu, q1.z, 16);
                pq.w = __shfl_xor_sync(0xffffffffu, q1.w, 16);
                pk.x = __shfl_xor_sync(0xffffffffu, k1.x, 16);
                pk.y = __shfl_xor_sync(0xffffffffu, k1.y, 16);
                pk.z = __shfl_xor_sync(0xffffffffu, k1.z, 16);
                pk.w = __shfl_xor_sync(0xffffffffu, k1.w, 16);
                q1.x = q1.x * csx + sgn * pq.x * snx;
                q1.y = q1.y * csy + sgn * pq.y * sny;
                q1.z = q1.z * csz + sgn * pq.z * snz;
                q1.w = q1.w * csw + sgn * pq.w * snw;
                k1.x = k1.x * csx + sgn * pk.x * snx;
                k1.y = k1.y * csy + sgn * pk.y * sny;
                k1.z = k1.z * csz + sgn * pk.z * snz;
                k1.w = k1.w * csw + sgn * pk.w * snw;
                float d10 = wred(q1.x * k0.x + q1.y * k0.y + q1.z * k0.z + q1.w * k0.w);
                float d11 = wred(q1.x * k1.x + q1.y * k1.y + q1.z * k1.z + q1.w * k1.w);
                const float scale = 0.08838834764831845f;
                float s10 = d10 * scale, s11 = d11 * scale;
                float m = fmaxf(s10, s11);
                float e0 = expf(s10 - m), e1 = expf(s11 - m);
                float inv = 1.f / (e0 + e1);
                if (lane == 0) { sc[0] = e0; sc[1] = e1; sc[2] = inv; }
                if ((b & 15) == 0) {
                    float4 v0 = ldcg4(g_qkv + 4096 + hh * HD + 4 * lane);
                    float4 v1 = ldcg4(g_qkv + 4096 + DIM + hh * HD + 4 * lane);
                    float* kv = kvc + (size_t)l * 4096;
                    ((float4*)(kv + hh * 256))[lane] = k0;
                    ((float4*)(kv + hh * 256 + HD))[lane] = k1;
                    ((float4*)(kv + 2048 + hh * 256))[lane] = v0;
                    ((float4*)(kv + 2048 + hh * 256 + HD))[lane] = v1;
                }
                __syncwarp();
                if (lane < 8) {
                    int dim = b * 8 + lane;
                    float v0 = ldcg(&g_qkv[4096 + dim]);
                    float v1 = ldcg(&g_qkv[4096 + DIM + dim]);
                    xs2[lane] = make_float2(v0, (sc[0] * v0 + sc[1] * v1) * sc[2]);
                }
            }
            CBAR();
            float4 A0 = {0,0,0,0}, A1 = {0,0,0,0};
            for (int st = 0; st < 2; st++) {
                STAGE_WAIT()
                const float4* b4 = (const float4*)buf;
#pragma unroll
                for (int r = 0; r < 4; r++) {
                    float4 w = b4[r * CTHR + tid];
                    float2 x = xs2[st * 4 + r];
                    A0.x = fmaf(w.x, x.x, A0.x); A0.y = fmaf(w.y, x.x, A0.y);
                    A0.z = fmaf(w.z, x.x, A0.z); A0.w = fmaf(w.w, x.x, A0.w);
                    A1.x = fmaf(w.x, x.y, A1.x); A1.y = fmaf(w.y, x.y, A1.y);
                    A1.z = fmaf(w.z, x.y, A1.z); A1.w = fmaf(w.w, x.y, A1.w);
                }
                STAGE_DONE()
            }
            red4(g_h + 4 * tid, A0);
            red4(g_h + DIM + 4 * tid, A1);
        }
        gbar(2 + 4 * l);

        // ===== GATEUP (b<256) =====
        if (b < 256) {
            int mat = b >> 7, rch = b & 127;
            float s0 = 0.f, s1 = 0.f;
#pragma unroll
            for (int i = 0; i < 4; i++) {
                int idx = tid + i * CTHR;
                float a = ldcg(&g_h[idx]), c = ldcg(&g_h[DIM + idx]);
                s0 += a * a; s1 += c * c;
            }
            s0 = bred256(s0, sbuf);
            s1 = bred256(s1, sbuf);
            float r0 = rsqrtf(s0 * (1.f / DIM) + EPSF);
            float r1 = rsqrtf(s1 * (1.f / DIM) + EPSF);
            if (tid < 8) {
                int idx = rch * 8 + tid;
                float wl = ln2[l * DIM + idx];
                xs2[tid] = make_float2(ldcg(&g_h[idx]) * r0 * wl,
                                       ldcg(&g_h[DIM + idx]) * r1 * wl);
            }
            CBAR();
            float4 A00 = {0,0,0,0}, A01 = {0,0,0,0}, A02 = {0,0,0,0}, A03 = {0,0,0,0};
            float4 A10 = {0,0,0,0}, A11 = {0,0,0,0}, A12 = {0,0,0,0}, A13 = {0,0,0,0};
            for (int st = 0; st < 8; st++) {   // 1 row per stage
                STAGE_WAIT()
                const float4* b4 = (const float4*)buf;
                float2 x = xs2[st];
                float4 w0 = b4[tid];
                float4 w1 = b4[CTHR + tid];
                float4 w2 = b4[2 * CTHR + tid];
                float4 w3 = b4[3 * CTHR + tid];
                A00.x = fmaf(w0.x, x.x, A00.x); A00.y = fmaf(w0.y, x.x, A00.y);
                A00.z = fmaf(w0.z, x.x, A00.z); A00.w = fmaf(w0.w, x.x, A00.w);
                A01.x = fmaf(w1.x, x.x, A01.x); A01.y = fmaf(w1.y, x.x, A01.y);
                A01.z = fmaf(w1.z, x.x, A01.z); A01.w = fmaf(w1.w, x.x, A01.w);
                A02.x = fmaf(w2.x, x.x, A02.x); A02.y = fmaf(w2.y, x.x, A02.y);
                A02.z = fmaf(w2.z, x.x, A02.z); A02.w = fmaf(w2.w, x.x, A02.w);
                A03.x = fmaf(w3.x, x.x, A03.x); A03.y = fmaf(w3.y, x.x, A03.y);
                A03.z = fmaf(w3.z, x.x, A03.z); A03.w = fmaf(w3.w, x.x, A03.w);
                A10.x = fmaf(w0.x, x.y, A10.x); A10.y = fmaf(w0.y, x.y, A10.y);
                A10.z = fmaf(w0.z, x.y, A10.z); A10.w = fmaf(w0.w, x.y, A10.w);
                A11.x = fmaf(w1.x, x.y, A11.x); A11.y = fmaf(w1.y, x.y, A11.y);
                A11.z = fmaf(w1.z, x.y, A11.z); A11.w = fmaf(w1.w, x.y, A11.w);
                A12.x = fmaf(w2.x, x.y, A12.x); A12.y = fmaf(w2.y, x.y, A12.y);
                A12.z = fmaf(w2.z, x.y, A12.z); A12.w = fmaf(w2.w, x.y, A12.w);
                A13.x = fmaf(w3.x, x.y, A13.x); A13.y = fmaf(w3.y, x.y, A13.y);
                A13.z = fmaf(w3.z, x.y, A13.z); A13.w = fmaf(w3.w, x.y, A13.w);
                STAGE_DONE()
            }
            float* o = g_gu + mat * 8192;
            red4(o + 4 * tid, A00);
            red4(o + 1024 + 4 * tid, A01);
            red4(o + 2048 + 4 * tid, A02);
            red4(o + 3072 + 4 * tid, A03);
            red4(o + FF + 4 * tid, A10);
            red4(o + FF + 1024 + 4 * tid, A11);
            red4(o + FF + 2048 + 4 * tid, A12);
            red4(o + FF + 3072 + 4 * tid, A13);
        } else {
            // idle blocks zero g_qkv for next layer (40 blocks, need 24)
            int idx = (b - 256) * CTHR + tid;
            if (idx < 6 * DIM) g_qkv[idx] = 0.f;
        }
        gbar(3 + 4 * l);

        // ===== DOWN (b<256) =====
        if (b < 256) {
            if (tid < 16) {
                int idx = b * 16 + tid;
                float g0 = ldcg(&g_gu[idx]);
                float g1 = ldcg(&g_gu[FF + idx]);
                float u0 = ldcg(&g_gu[8192 + idx]);
                float u1 = ldcg(&g_gu[8192 + FF + idx]);
                xs2[tid] = make_float2(g0 / (1.f + expf(-g0)) * u0,
                                       g1 / (1.f + expf(-g1)) * u1);
            }
            CBAR();
            float4 A0 = {0,0,0,0}, A1 = {0,0,0,0};
            for (int st = 0; st < 4; st++) {
                STAGE_WAIT()
                const float4* b4 = (const float4*)buf;
#pragma unroll
                for (int r = 0; r < 4; r++) {
                    float4 w = b4[r * CTHR + tid];
                    float2 x = xs2[st * 4 + r];
                    A0.x = fmaf(w.x, x.x, A0.x); A0.y = fmaf(w.y, x.x, A0.y);
                    A0.z = fmaf(w.z, x.x, A0.z); A0.w = fmaf(w.w, x.x, A0.w);
                    A1.x = fmaf(w.x, x.y, A1.x); A1.y = fmaf(w.y, x.y, A1.y);
                    A1.z = fmaf(w.z, x.y, A1.z); A1.w = fmaf(w.w, x.y, A1.w);
                }
                STAGE_DONE()
            }
            red4(g_h + 4 * tid, A0);
            red4(g_h + DIM + 4 * tid, A1);
        }
        gbar(4 + 4 * l);
    }

    // ===== LM (all blocks, uniform chunks) =====
    {
        float s = 0.f;
#pragma unroll
        for (int i = 0; i < 4; i++) {
            float v = ldcg(&g_h[DIM + tid + i * CTHR]);
            s += v * v;
        }
        s = bred256(s, sbuf);
        float r = rsqrtf(s * (1.f / DIM) + EPSF);
#pragma unroll
        for (int i = 0; i < 4; i++) {
            int idx = tid + i * CTHR;
            xsf[idx] = ldcg(&g_h[DIM + idx]) * r * fn[idx];
        }
        CBAR();

        for (int c = c0; c < c1; c++) {
            int mat = c >> 6, rowbase = (c & 63) * 16;
            float4 A0 = {0,0,0,0}, A1 = {0,0,0,0};
            for (int st = 0; st < 8; st++) {   // 2 rows per stage
                STAGE_WAIT()
                const float4* b4 = (const float4*)buf;
#pragma unroll
                for (int r2 = 0; r2 < 2; r2++) {
                    float x = xsf[rowbase + st * 2 + r2];
                    float4 w0 = b4[r2 * 512 + tid];
                    float4 w1 = b4[r2 * 512 + CTHR + tid];
                    A0.x = fmaf(w0.x, x, A0.x); A0.y = fmaf(w0.y, x, A0.y);
                    A0.z = fmaf(w0.z, x, A0.z); A0.w = fmaf(w0.w, x, A0.w);
                    A1.x = fmaf(w1.x, x, A1.x); A1.y = fmaf(w1.y, x, A1.y);
                    A1.z = fmaf(w1.z, x, A1.z); A1.w = fmaf(w1.w, x, A1.w);
                }
                STAGE_DONE()
            }
            red4(logits + (size_t)mat * VOC + 4 * tid, A0);
            red4(logits + (size_t)mat * VOC + 1024 + 4 * tid, A1);
        }
    }

    CBAR();
    if (tid == 0) {
        unsigned old = atomicAdd(&g_fin, 1u);
        if (old == (unsigned)(NBLK - 1)) {
            for (int i = 0; i < 21; i++) g_bar[i] = 0u;
            __threadfence();
            g_fin = 0u;
        }
    }
}

// ---------------- host launcher ----------------
extern "C" void kernel_launch(void* const* d_in, const int* in_sizes, int n_in,
                              void* d_out, int out_size) {
    const float *past, *emb, *Wq, *Wk, *Wv, *Wo, *qn, *kn, *ln1, *ln2, *Wg, *Wu,
        *Wd, *fn, *lm;
    const int* tok;
    if (in_sizes[1] == 1) {
        past = (const float*)d_in[0];
        tok  = (const int*)d_in[1];
        emb  = (const float*)d_in[2];
        Wq = (const float*)d_in[3];  Wk = (const float*)d_in[4];
        Wv = (const float*)d_in[5];  Wo = (const float*)d_in[6];
        qn = (const float*)d_in[7];  kn = (const float*)d_in[8];
        ln1 = (const float*)d_in[9]; ln2 = (const float*)d_in[10];
        Wg = (const float*)d_in[11]; Wu = (const float*)d_in[12];
        Wd = (const float*)d_in[13]; fn = (const float*)d_in[14];
        lm = (const float*)d_in[15];
    } else {
        past = (const float*)d_in[0];
        emb  = (const float*)d_in[1];
        Wq = (const float*)d_in[2];  Wk = (const float*)d_in[3];
        Wv = (const float*)d_in[4];  Wo = (const float*)d_in[5];
        qn = (const float*)d_in[6];  kn = (const float*)d_in[7];
        ln1 = (const float*)d_in[8]; ln2 = (const float*)d_in[9];
        Wg = (const float*)d_in[10]; Wu = (const float*)d_in[11];
        Wd = (const float*)d_in[12]; fn = (const float*)d_in[13];
        lm = (const float*)d_in[14];
        tok = (const int*)d_in[15];
    }

    static bool attr_done = false;
    if (!attr_done) {
        cudaFuncSetAttribute(k_mega, cudaFuncAttributeMaxDynamicSharedMemorySize,
                             SM_TOTAL);
        attr_done = true;
    }

    float* out = (float*)d_out;
    float* logits = out;
    float* kvc = out + NLM * VOC;

    k_mega<<<NBLK, NTHR, SM_TOTAL>>>(past, emb, tok, Wq, Wk, Wv, Wo, qn, kn,
                                     ln1, ln2, Wg, Wu, Wd, fn, lm, logits, kvc);
    (void)n_in; (void)out_size;
}

// round 12
// speedup vs baseline: 1.3846x; 1.1111x over previous
#include <cuda_runtime.h>
#include <cuda_bf16.h>
#include <math.h>
#include <stdint.h>

#define DIM    1024
#define HD     128
#define FF     4096
#define VOC    2048
#define NLM    15
#define NLAYER 5
#define EPSF   1e-6f
#define NBLK   148
#define CTHR   512          // compute threads
#define NTHR   544          // + producer warp
#define NWARP  16

#define NBUF         12
#define STAGE_BYTES  16384
#define STAGE_FLOATS 4096
#define MBF_OFF  0
#define MBE_OFF  96
#define SC_OFF   192
#define XS_OFF   256
#define SBUF_OFF 4352
#define TAB_OFF  4480
#define ST_OFF   8192
#define SM_TOTAL (ST_OFF + NBUF * STAGE_BYTES)   // 204800

#define N_STICKY_MATS 6    // 6 lm heads = 50MB, sized to fit HW sticky L2 region

// ---------------- device scratch ----------------
__device__ float g_h[2 * DIM];
__device__ float g_qkv[6 * DIM];
__device__ float g_gu[4 * FF];
__device__ unsigned g_bar[32];
__device__ unsigned g_fin;

// ---------------- PTX helpers ----------------
__device__ __forceinline__ uint32_t s2u(const void* p) {
    uint32_t a;
    asm("{ .reg .u64 t; cvta.to.shared.u64 t, %1; cvt.u32.u64 %0, t; }"
        : "=r"(a) : "l"(p));
    return a;
}
#define MB_INIT(mbar, cnt) \
    asm volatile("mbarrier.init.shared.b64 [%0], %1;" :: "r"(mbar), "r"(cnt) : "memory")
#define MB_EXPECT(mbar, bytes) \
    asm volatile("mbarrier.arrive.expect_tx.shared.b64 _, [%0], %1;" :: "r"(mbar), "r"(bytes) : "memory")
#define MB_ARRIVE(mbar) \
    asm volatile("mbarrier.arrive.shared.b64 _, [%0];" :: "r"(mbar) : "memory")
#define MB_WAIT(mbar, ph) do {                                                   \
    asm volatile("{\n\t.reg .pred P1;\n\t"                                       \
        "W_%=:\n\t"                                                              \
        "mbarrier.try_wait.parity.acquire.cta.shared::cta.b64 P1, [%0], %1, 0x989680;\n\t" \
        "@P1 bra.uni D_%=;\n\t"                                                  \
        "bra.uni W_%=;\n\t"                                                      \
        "D_%=:\n\t}"                                                             \
        :: "r"(mbar), "r"(ph) : "memory");                                       \
} while (0)
#define CBAR() asm volatile("bar.sync 1, %0;" :: "n"(CTHR) : "memory")
__device__ __forceinline__ void bulk_g2s_h(uint32_t dst, const void* src,
                                           uint32_t bytes, uint32_t mbar,
                                           uint64_t pol) {
    asm volatile(
        "cp.async.bulk.shared::cluster.global.mbarrier::complete_tx::bytes"
        ".L2::cache_hint [%0], [%1], %2, [%3], %4;"
        :: "r"(dst), "l"(src), "r"(bytes), "r"(mbar), "l"(pol) : "memory");
}
__device__ __forceinline__ void red2(float* p, float a, float b) {
    asm volatile("red.global.add.v2.f32 [%0], {%1, %2};"
                 :: "l"(p), "f"(a), "f"(b) : "memory");
}
__device__ __forceinline__ void red4(float* p, float4 v) {
    asm volatile("red.global.add.v4.f32 [%0], {%1, %2, %3, %4};"
                 :: "l"(p), "f"(v.x), "f"(v.y), "f"(v.z), "f"(v.w) : "memory");
}
__device__ __forceinline__ float ldcg(const float* p) {
    float v;
    asm volatile("ld.global.cg.f32 %0, [%1];" : "=f"(v) : "l"(p));
    return v;
}
__device__ __forceinline__ float4 ldcg4(const float* p) {
    float4 v;
    asm volatile("ld.global.cg.v4.f32 {%0,%1,%2,%3}, [%4];"
                 : "=f"(v.x), "=f"(v.y), "=f"(v.z), "=f"(v.w) : "l"(p));
    return v;
}

// ---------------- reductions ----------------
__device__ __forceinline__ float wred(float v) {
#pragma unroll
    for (int o = 16; o > 0; o >>= 1) v += __shfl_xor_sync(0xffffffffu, v, o);
    return v;
}
__device__ __forceinline__ float bred512(float v, float* sbuf) {
    int tid = threadIdx.x;
#pragma unroll
    for (int o = 16; o > 0; o >>= 1) v += __shfl_down_sync(0xffffffffu, v, o);
    if ((tid & 31) == 0) sbuf[tid >> 5] = v;
    CBAR();
    if (tid < 32) {
        float r = (tid < 16) ? sbuf[tid] : 0.f;
#pragma unroll
        for (int o = 8; o > 0; o >>= 1) r += __shfl_down_sync(0xffffffffu, r, o);
        if (tid == 0) sbuf[0] = r;
    }
    CBAR();
    float r = sbuf[0];
    CBAR();
    return r;
}

__device__ __forceinline__ void gbar(int idx) {
    __threadfence();
    CBAR();
    if (threadIdx.x == 0) {
        atomicAdd(&g_bar[idx], 1u);
        unsigned v;
        while (true) {
            asm volatile("ld.acquire.gpu.global.u32 %0, [%1];"
                         : "=r"(v) : "l"(&g_bar[idx]) : "memory");
            if (v >= (unsigned)NBLK) break;
            __nanosleep(64);
        }
    }
    CBAR();
}

// consume: per-warp arrivals, warps pipeline freely
#define CONSUME_BEGIN(nst)                                                     \
    for (int _i = 0; _i < (nst); _i++) {                                       \
        int _slot = consumed % NBUF, _par = (consumed / NBUF) & 1;             \
        MB_WAIT(mbf + 8u * _slot, _par);                                       \
        const float* buf = (const float*)(sm + ST_OFF + _slot * STAGE_BYTES);

#define CONSUME_END                                                            \
        __syncwarp();                                                          \
        if ((tid & 31) == 0) MB_ARRIVE(mbe + 8u * _slot);                      \
        consumed++;                                                            \
    }

// ---------------- mega kernel ----------------
__global__ void __launch_bounds__(NTHR) k_mega(
    const float* __restrict__ past, const float* __restrict__ emb,
    const int* __restrict__ tok,
    const float* __restrict__ Wq, const float* __restrict__ Wk,
    const float* __restrict__ Wv, const float* __restrict__ Wo,
    const float* __restrict__ qn, const float* __restrict__ kn,
    const float* __restrict__ ln1, const float* __restrict__ ln2,
    const float* __restrict__ Wg, const float* __restrict__ Wu,
    const float* __restrict__ Wd, const float* __restrict__ fn,
    const float* __restrict__ lm,
    float* __restrict__ logits, float* __restrict__ kvc) {
    extern __shared__ char sm[];
    const int b = blockIdx.x;
    const int tid = threadIdx.x;
    const uint32_t mbf = s2u(sm) + MBF_OFF;
    const uint32_t mbe = s2u(sm) + MBE_OFF;
    float* sbuf = (float*)(sm + SBUF_OFF);
    float2* xs2 = (float2*)(sm + XS_OFF);
    float* xsf = (float*)(sm + XS_OFF);
    float* sc = (float*)(sm + SC_OFF);
    int c0 = (b * 960) / NBLK, c1 = ((b + 1) * 960) / NBLK;   // uniform lm split

    if (tid == CTHR) {
#pragma unroll
        for (int s = 0; s < NBUF; s++) {
            MB_INIT(mbf + 8u * s, 1);
            MB_INIT(mbe + 8u * s, NWARP);
        }
    }
    __syncthreads();

    // ================= producer warp =================
    if (tid >= CTHR) {
        if (tid == CTHR) {
            uint64_t pol_keep, pol_stream;
            asm volatile("createpolicy.fractional.L2::evict_last.b64 %0, 1.0;"
                         : "=l"(pol_keep));
            asm volatile("createpolicy.fractional.L2::evict_first.b64 %0, 1.0;"
                         : "=l"(pol_stream));
            uintptr_t* tab = (uintptr_t*)(sm + TAB_OFF);
            int n = 0;
            for (int l = 0; l < NLAYER; l++) {
                if (b < 96) {
                    const float* W = (b >> 5) == 0 ? Wq : ((b >> 5) == 1 ? Wk : Wv);
                    const float* base = W + (size_t)l * DIM * DIM +
                                        (size_t)(b & 31) * 32 * DIM;
                    for (int s = 0; s < 8; s++)
                        tab[n++] = (uintptr_t)(base + (size_t)s * STAGE_FLOATS);
                }
                if (b < 64) {
                    const float* base = Wo + (size_t)l * DIM * DIM +
                                        (size_t)b * 16 * DIM;
                    for (int s = 0; s < 4; s++)
                        tab[n++] = (uintptr_t)(base + (size_t)s * STAGE_FLOATS);
                }
                if (b < 128) {
                    const float* W = (b >> 6) ? Wu : Wg;
                    const float* base = W + (size_t)l * DIM * FF +
                                        (size_t)(b & 63) * 16 * FF;
                    for (int s = 0; s < 16; s++)
                        tab[n++] = (uintptr_t)(base + (size_t)s * STAGE_FLOATS);
                }
                if (b < 128) {
                    const float* base = Wd + (size_t)l * FF * DIM +
                                        (size_t)b * 32 * DIM;
                    for (int s = 0; s < 8; s++)
                        tab[n++] = (uintptr_t)(base + (size_t)s * STAGE_FLOATS);
                }
            }
            for (int c = c0; c < c1; c++) {
                int mat = c >> 6;
                uintptr_t flag = (mat < N_STICKY_MATS) ? 1u : 0u;
                const float* base = lm + (size_t)mat * DIM * VOC +
                                    (size_t)(c & 63) * 16 * VOC;
                for (int s = 0; s < 8; s++)
                    tab[n++] = ((uintptr_t)(base + (size_t)s * STAGE_FLOATS)) | flag;
            }
            for (int i = 0; i < n; i++) {
                int slot = i % NBUF;
                if (i >= NBUF) {
                    int par = ((i / NBUF) - 1) & 1;
                    MB_WAIT(mbe + 8u * slot, par);
                }
                uintptr_t e = tab[i];
                uint64_t pol = (e & 1u) ? pol_keep : pol_stream;
                const void* src = (const void*)(e & ~(uintptr_t)1u);
                MB_EXPECT(mbf + 8u * slot, STAGE_BYTES);
                bulk_g2s_h(s2u(sm) + ST_OFF + slot * STAGE_BYTES, src,
                           STAGE_BYTES, mbf + 8u * slot, pol);
            }
        }
        return;
    }

    // ================= compute threads (512) =================
    int consumed = 0;

    {
        int gi = b * CTHR + tid;
        if (gi < NLM * VOC) logits[gi] = 0.f;
        else if (gi < NLM * VOC + 6 * DIM) g_qkv[gi - NLM * VOC] = 0.f;
        else if (gi < NLM * VOC + 6 * DIM + DIM) {
            int i = gi - (NLM * VOC + 6 * DIM);
            g_h[i] = past[i];
        } else if (gi < NLM * VOC + 6 * DIM + 2 * DIM) {
            int i = gi - (NLM * VOC + 7 * DIM);
            g_h[DIM + i] = emb[(size_t)tok[0] * DIM + i];
        }
    }
    gbar(0);

    for (int l = 0; l < NLAYER; l++) {
        // ===== QKV =====
        if (b < 96) {
            int mat = b >> 5, rch = b & 31;
            float s0 = 0.f, s1 = 0.f;
#pragma unroll
            for (int i = 0; i < 2; i++) {
                int idx = tid + i * CTHR;
                float a = ldcg(&g_h[idx]), c = ldcg(&g_h[DIM + idx]);
                s0 += a * a; s1 += c * c;
            }
            s0 = bred512(s0, sbuf);
            s1 = bred512(s1, sbuf);
            float r0 = rsqrtf(s0 * (1.f / DIM) + EPSF);
            float r1 = rsqrtf(s1 * (1.f / DIM) + EPSF);
            if (tid < 32) {
                int idx = rch * 32 + tid;
                float wl = ln1[l * DIM + idx];
                xs2[tid] = make_float2(ldcg(&g_h[idx]) * r0 * wl,
                                       ldcg(&g_h[DIM + idx]) * r1 * wl);
            }
            CBAR();
            float a00 = 0.f, a01 = 0.f, a10 = 0.f, a11 = 0.f;
            CONSUME_BEGIN(8)
                const float2* bw = (const float2*)buf;
#pragma unroll
                for (int r = 0; r < 4; r++) {
                    float2 w = bw[r * CTHR + tid];
                    float2 x = xs2[_i * 4 + r];
                    a00 = fmaf(w.x, x.x, a00); a01 = fmaf(w.y, x.x, a01);
                    a10 = fmaf(w.x, x.y, a10); a11 = fmaf(w.y, x.y, a11);
                }
            CONSUME_END
            float* o = g_qkv + mat * 2048;
            red2(o + 2 * tid, a00, a01);
            red2(o + DIM + 2 * tid, a10, a11);
        } else if (b < 128) {
            g_gu[(b - 96) * CTHR + tid] = 0.f;
        }
        gbar(1 + 4 * l);

        // ===== WO + attention =====
        if (b < 64) {
            int hh = b >> 3;
            if (tid < 32) {
                int lane = tid;
                float4 q1 = ldcg4(g_qkv + DIM + hh * HD + 4 * lane);
                float4 k0 = ldcg4(g_qkv + 2048 + hh * HD + 4 * lane);
                float4 k1 = ldcg4(g_qkv + 2048 + DIM + hh * HD + 4 * lane);
                float nq1 = wred(q1.x * q1.x + q1.y * q1.y + q1.z * q1.z + q1.w * q1.w);
                float nk0 = wred(k0.x * k0.x + k0.y * k0.y + k0.z * k0.z + k0.w * k0.w);
                float nk1 = wred(k1.x * k1.x + k1.y * k1.y + k1.z * k1.z + k1.w * k1.w);
                float rq1 = rsqrtf(nq1 * (1.f / HD) + EPSF);
                float rk0 = rsqrtf(nk0 * (1.f / HD) + EPSF);
                float rk1 = rsqrtf(nk1 * (1.f / HD) + EPSF);
                float4 qn4 = ((const float4*)(qn + l * HD))[lane];
                float4 kn4 = ((const float4*)(kn + l * HD))[lane];
                q1.x *= rq1 * qn4.x; q1.y *= rq1 * qn4.y;
                q1.z *= rq1 * qn4.z; q1.w *= rq1 * qn4.w;
                k0.x *= rk0 * kn4.x; k0.y *= rk0 * kn4.y;
                k0.z *= rk0 * kn4.z; k0.w *= rk0 * kn4.w;
                k1.x *= rk1 * kn4.x; k1.y *= rk1 * kn4.y;
                k1.z *= rk1 * kn4.z; k1.w *= rk1 * kn4.w;
                int jb = 4 * (lane & 15);
                const float C = 9.210340371976184f / 64.f;
                float an0 = expf(-(float)(jb + 0) * C);
                float an1 = expf(-(float)(jb + 1) * C);
                float an2 = expf(-(float)(jb + 2) * C);
                float an3 = expf(-(float)(jb + 3) * C);
                float csx = cosf(an0), snx = sinf(an0);
                float csy = cosf(an1), sny = sinf(an1);
                float csz = cosf(an2), snz = sinf(an2);
                float csw = cosf(an3), snw = sinf(an3);
                float sgn = (lane < 16) ? -1.f : 1.f;
                float4 pq, pk;
                pq.x = __shfl_xor_sync(0xffffffffu, q1.x, 16);
                pq.y = __shfl_xor_sync(0xffffffffu, q1.y, 16);
                pq.z = __shfl_xor_sync(0xffffffffu, q1.z, 16);
                pq.w = __shfl_xor_sync(0xffffffffu, q1.w, 16);
                pk.x = __shfl_xor_sync(0xffffffffu, k1.x, 16);
                pk.y = __shfl_xor_sync(0xffffffffu, k1.y, 16);
                pk.z = __shfl_xor_sync(0xffffffffu, k1.z, 16);
                pk.w = __shfl_xor_sync(0xffffffffu, k1.w, 16);
                q1.x = q1.x * csx + sgn * pq.x * snx;
                q1.y = q1.y * csy + sgn * pq.y * sny;
                q1.z = q1.z * csz + sgn * pq.z * snz;
                q1.w = q1.w * csw + sgn * pq.w * snw;
                k1.x = k1.x * csx + sgn * pk.x * snx;
                k1.y = k1.y * csy + sgn * pk.y * sny;
                k1.z = k1.z * csz + sgn * pk.z * snz;
                k1.w = k1.w * csw + sgn * pk.w * snw;
                float d10 = wred(q1.x * k0.x + q1.y * k0.y + q1.z * k0.z + q1.w * k0.w);
                float d11 = wred(q1.x * k1.x + q1.y * k1.y + q1.z * k1.z + q1.w * k1.w);
                const float scale = 0.08838834764831845f;
                float s10 = d10 * scale, s11 = d11 * scale;
                float m = fmaxf(s10, s11);
                float e0 = expf(s10 - m), e1 = expf(s11 - m);
                float inv = 1.f / (e0 + e1);
                if (lane == 0) { sc[0] = e0; sc[1] = e1; sc[2] = inv; }
                if ((b & 7) == 0) {
                    float4 v0 = ldcg4(g_qkv + 4096 + hh * HD + 4 * lane);
                    float4 v1 = ldcg4(g_qkv + 4096 + DIM + hh * HD + 4 * lane);
                    float* kv = kvc + (size_t)l * 4096;
                    ((float4*)(kv + hh * 256))[lane] = k0;
                    ((float4*)(kv + hh * 256 + HD))[lane] = k1;
                    ((float4*)(kv + 2048 + hh * 256))[lane] = v0;
                    ((float4*)(kv + 2048 + hh * 256 + HD))[lane] = v1;
                }
            }
            CBAR();
            if (tid < 16) {
                int dim = b * 16 + tid;
                float v0 = ldcg(&g_qkv[4096 + dim]);
                float v1 = ldcg(&g_qkv[4096 + DIM + dim]);
                xs2[tid] = make_float2(v0, (sc[0] * v0 + sc[1] * v1) * sc[2]);
            }
            CBAR();
            float a00 = 0.f, a01 = 0.f, a10 = 0.f, a11 = 0.f;
            CONSUME_BEGIN(4)
                const float2* bw = (const float2*)buf;
#pragma unroll
                for (int r = 0; r < 4; r++) {
                    float2 w = bw[r * CTHR + tid];
                    float2 x = xs2[_i * 4 + r];
                    a00 = fmaf(w.x, x.x, a00); a01 = fmaf(w.y, x.x, a01);
                    a10 = fmaf(w.x, x.y, a10); a11 = fmaf(w.y, x.y, a11);
                }
            CONSUME_END
            red2(g_h + 2 * tid, a00, a01);
            red2(g_h + DIM + 2 * tid, a10, a11);
        }
        gbar(2 + 4 * l);

        // ===== GATEUP =====
        if (b < 128) {
            int mat = b >> 6, rch = b & 63;
            float s0 = 0.f, s1 = 0.f;
#pragma unroll
            for (int i = 0; i < 2; i++) {
                int idx = tid + i * CTHR;
                float a = ldcg(&g_h[idx]), c = ldcg(&g_h[DIM + idx]);
                s0 += a * a; s1 += c * c;
            }
            s0 = bred512(s0, sbuf);
            s1 = bred512(s1, sbuf);
            float r0 = rsqrtf(s0 * (1.f / DIM) + EPSF);
            float r1 = rsqrtf(s1 * (1.f / DIM) + EPSF);
            if (tid < 16) {
                int idx = rch * 16 + tid;
                float wl = ln2[l * DIM + idx];
                xs2[tid] = make_float2(ldcg(&g_h[idx]) * r0 * wl,
                                       ldcg(&g_h[DIM + idx]) * r1 * wl);
            }
            CBAR();
            float4 A00 = {0,0,0,0}, A01 = {0,0,0,0}, A10 = {0,0,0,0}, A11 = {0,0,0,0};
            CONSUME_BEGIN(16)
                const float4* b4 = (const float4*)buf;
                float2 x = xs2[_i];
                float4 w0 = b4[tid];
                float4 w1 = b4[CTHR + tid];
                A00.x = fmaf(w0.x, x.x, A00.x); A00.y = fmaf(w0.y, x.x, A00.y);
                A00.z = fmaf(w0.z, x.x, A00.z); A00.w = fmaf(w0.w, x.x, A00.w);
                A10.x = fmaf(w0.x, x.y, A10.x); A10.y = fmaf(w0.y, x.y, A10.y);
                A10.z = fmaf(w0.z, x.y, A10.z); A10.w = fmaf(w0.w, x.y, A10.w);
                A01.x = fmaf(w1.x, x.x, A01.x); A01.y = fmaf(w1.y, x.x, A01.y);
                A01.z = fmaf(w1.z, x.x, A01.z); A01.w = fmaf(w1.w, x.x, A01.w);
                A11.x = fmaf(w1.x, x.y, A11.x); A11.y = fmaf(w1.y, x.y, A11.y);
                A11.z = fmaf(w1.z, x.y, A11.z); A11.w = fmaf(w1.w, x.y, A11.w);
            CONSUME_END
            float* o = g_gu + mat * 8192;
            red4(o + 4 * tid, A00);
            red4(o + 2048 + 4 * tid, A01);
            red4(o + FF + 4 * tid, A10);
            red4(o + FF + 2048 + 4 * tid, A11);
        }
        gbar(3 + 4 * l);

        // ===== DOWN =====
        if (b < 128) {
            if (tid < 32) {
                int idx = b * 32 + tid;
                float g0 = ldcg(&g_gu[idx]);
                float g1 = ldcg(&g_gu[FF + idx]);
                float u0 = ldcg(&g_gu[8192 + idx]);
                float u1 = ldcg(&g_gu[8192 + FF + idx]);
                xs2[tid] = make_float2(g0 / (1.f + expf(-g0)) * u0,
                                       g1 / (1.f + expf(-g1)) * u1);
            }
            CBAR();
            float a00 = 0.f, a01 = 0.f, a10 = 0.f, a11 = 0.f;
            CONSUME_BEGIN(8)
                const float2* bw = (const float2*)buf;
#pragma unroll
                for (int r = 0; r < 4; r++) {
                    float2 w = bw[r * CTHR + tid];
                    float2 x = xs2[_i * 4 + r];
                    a00 = fmaf(w.x, x.x, a00); a01 = fmaf(w.y, x.x, a01);
                    a10 = fmaf(w.x, x.y, a10); a11 = fmaf(w.y, x.y, a11);
                }
            CONSUME_END
            red2(g_h + 2 * tid, a00, a01);
            red2(g_h + DIM + 2 * tid, a10, a11);
        }
        if (b < 12) g_qkv[b * CTHR + tid] = 0.f;
        gbar(4 + 4 * l);
    }

    // ===== LM =====
    {
        float s = 0.f;
#pragma unroll
        for (int i = 0; i < 2; i++) {
            float v = ldcg(&g_h[DIM + tid + i * CTHR]);
            s += v * v;
        }
        s = bred512(s, sbuf);
        float r = rsqrtf(s * (1.f / DIM) + EPSF);
#pragma unroll
        for (int i = 0; i < 2; i++) {
            int idx = tid + i * CTHR;
            xsf[idx] = ldcg(&g_h[DIM + idx]) * r * fn[idx];
        }
        CBAR();

        float4 A = {0, 0, 0, 0};
        int curmat = -1;
        for (int c = c0; c < c1; c++) {
            int mat = c >> 6;
            if (mat != curmat) {
                if (curmat >= 0)
                    red4(logits + (size_t)curmat * VOC + 4 * tid, A);
                A = make_float4(0.f, 0.f, 0.f, 0.f);
                curmat = mat;
            }
            int rbase0 = (c & 63) * 16;
            CONSUME_BEGIN(8)
                const float4* b4 = (const float4*)buf;
#pragma unroll
                for (int r = 0; r < 2; r++) {
                    float x = xsf[rbase0 + _i * 2 + r];
                    float4 w = b4[r * CTHR + tid];
                    A.x = fmaf(w.x, x, A.x); A.y = fmaf(w.y, x, A.y);
                    A.z = fmaf(w.z, x, A.z); A.w = fmaf(w.w, x, A.w);
                }
            CONSUME_END
        }
        if (curmat >= 0) red4(logits + (size_t)curmat * VOC + 4 * tid, A);
    }

    CBAR();
    if (tid == 0) {
        unsigned old = atomicAdd(&g_fin, 1u);
        if (old == (unsigned)(NBLK - 1)) {
            for (int i = 0; i < 21; i++) g_bar[i] = 0u;
            __threadfence();
            g_fin = 0u;
        }
    }
}

// ---------------- host launcher ----------------
extern "C" void kernel_launch(void* const* d_in, const int* in_sizes, int n_in,
                              void* d_out, int out_size) {
    const float *past, *emb, *Wq, *Wk, *Wv, *Wo, *qn, *kn, *ln1, *ln2, *Wg, *Wu,
        *Wd, *fn, *lm;
    const int* tok;
    if (in_sizes[1] == 1) {
        past = (const float*)d_in[0];
        tok  = (const int*)d_in[1];
        emb  = (const float*)d_in[2];
        Wq = (const float*)d_in[3];  Wk = (const float*)d_in[4];
        Wv = (const float*)d_in[5];  Wo = (const float*)d_in[6];
        qn = (const float*)d_in[7];  kn = (const float*)d_in[8];
        ln1 = (const float*)d_in[9]; ln2 = (const float*)d_in[10];
        Wg = (const float*)d_in[11]; Wu = (const float*)d_in[12];
        Wd = (const float*)d_in[13]; fn = (const float*)d_in[14];
        lm = (const float*)d_in[15];
    } else {
        past = (const float*)d_in[0];
        emb  = (const float*)d_in[1];
        Wq = (const float*)d_in[2];  Wk = (const float*)d_in[3];
        Wv = (const float*)d_in[4];  Wo = (const float*)d_in[5];
        qn = (const float*)d_in[6];  kn = (const float*)d_in[7];
        ln1 = (const float*)d_in[8]; ln2 = (const float*)d_in[9];
        Wg = (const float*)d_in[10]; Wu = (const float*)d_in[11];
        Wd = (const float*)d_in[12]; fn = (const float*)d_in[13];
        lm = (const float*)d_in[14];
        tok = (const int*)d_in[15];
    }

    static bool attr_done = false;
    if (!attr_done) {
        cudaFuncSetAttribute(k_mega, cudaFuncAttributeMaxDynamicSharedMemorySize,
                             SM_TOTAL);
        attr_done = true;
    }

    float* out = (float*)d_out;
    float* logits = out;
    float* kvc = out + NLM * VOC;

    k_mega<<<NBLK, NTHR, SM_TOTAL>>>(past, emb, tok, Wq, Wk, Wv, Wo, qn, kn,
                                     ln1, ln2, Wg, Wu, Wd, fn, lm, logits, kvc);
    (void)n_in; (void)out_size;
}